// round 1
// baseline (speedup 1.0000x reference)
#include <cuda_runtime.h>
#include <cuda_bf16.h>
#include <cstdint>

// ---------------- problem constants ----------------
#define B_     16
#define L_     8192
#define IN_    57
#define DM     64
#define DS     32
#define HD     32
#define NH     4
#define DI     128          // EXP*DM
#define DPROJ  324          // 2*DI + 2*DS + NH
#define NL     2
#define OUT_   6
#define Q      64           // chunk length
#define NCH    (L_ / Q)     // 128 chunks
#define BL     (B_ * L_)    // 131072 rows

// ---------------- scratch (device globals; allocation-free) ----------------
__device__ float g_h [BL * DM];          // hidden stream          33.5 MB
__device__ float g_X [BL * DI];          // silu(xin)              67 MB
__device__ float g_Z [BL * DI];          // silu(z)                67 MB
__device__ float g_y [BL * DI];          // scan output (gated)    67 MB
__device__ float g_Bm[BL * DS];          // silu(B)                16.8 MB
__device__ float g_Cm[BL * DS];          // silu(C)                16.8 MB
__device__ float g_dt[BL * NH];          // softplus(dt+bias)      2.1 MB
__device__ float g_la[BL * NH];          // within-chunk cumsum(dt*A)
__device__ float g_Sd[B_ * NH * NCH * HD * DS];  // chunk delta states 33.5 MB
__device__ float g_h0[B_ * NH * NCH * HD * DS];  // chunk entry states 33.5 MB
__device__ float g_aQ[B_ * NH * NCH];            // chunk total decay

// ---------------- helpers ----------------
__device__ __forceinline__ float siluf(float v) {
    return v / (1.f + __expf(-v));
}
__device__ __forceinline__ float softplusf(float v) {
    return (v > 20.f) ? v : log1pf(__expf(v));
}

// ================= K1: linear_in  h = x @ W_in + b_in =================
__global__ void k_linear_in(const float* __restrict__ x,
                            const float* __restrict__ W,
                            const float* __restrict__ bias) {
    const int row0 = blockIdx.x * 16;
    __shared__ float sx[16][IN_ + 1];
    __shared__ float sw[IN_][DM];
    const int tid = threadIdx.x;
    for (int idx = tid; idx < 16 * IN_; idx += 256) {
        int r = idx / IN_, k = idx % IN_;
        sx[r][k] = x[(size_t)(row0 + r) * IN_ + k];
    }
    for (int idx = tid; idx < IN_ * DM; idx += 256)
        sw[idx / DM][idx % DM] = W[idx];
    __syncthreads();
    const int c = tid & 63, q = tid >> 6;
    float bc = bias[c];
    float acc[4] = {bc, bc, bc, bc};
    for (int k = 0; k < IN_; k++) {
        float wv = sw[k][c];
#pragma unroll
        for (int j = 0; j < 4; j++) acc[j] += sx[q * 4 + j][k] * wv;
    }
#pragma unroll
    for (int j = 0; j < 4; j++)
        g_h[(size_t)(row0 + q * 4 + j) * DM + c] = acc[j];
}

// ================= K2: fused in_proj + activations =================
__global__ void k_inproj(const float* __restrict__ W,      // [NL, DM, DPROJ]
                         const float* __restrict__ bias,   // [NL, DPROJ]
                         const float* __restrict__ dt_bias,// [NL, NH]
                         int l) {
    const int row0 = blockIdx.x * 16;
    __shared__ float shT[DM][20];   // h tile transposed, padded for f4 + banks
    const int tid = threadIdx.x;
    for (int idx = tid; idx < 16 * DM; idx += 256) {
        int r = idx >> 6, k = idx & 63;
        shT[k][r] = g_h[(size_t)(row0 + r) * DM + k];
    }
    __syncthreads();
    const float* Wl = W + (size_t)l * DM * DPROJ;
    const float* bl = bias + l * DPROJ;

    for (int pass = 0; pass < 2; pass++) {
        int c = (pass == 0) ? tid : 256 + tid;
        if (c < DPROJ) {
            float bc = bl[c];
            float acc[16];
#pragma unroll
            for (int r = 0; r < 16; r++) acc[r] = bc;
            for (int k = 0; k < DM; k++) {
                float wv = __ldg(&Wl[(size_t)k * DPROJ + c]);
                const float4* row4 = reinterpret_cast<const float4*>(&shT[k][0]);
                float4 h0v = row4[0], h1v = row4[1], h2v = row4[2], h3v = row4[3];
                acc[0]  += h0v.x * wv; acc[1]  += h0v.y * wv; acc[2]  += h0v.z * wv; acc[3]  += h0v.w * wv;
                acc[4]  += h1v.x * wv; acc[5]  += h1v.y * wv; acc[6]  += h1v.z * wv; acc[7]  += h1v.w * wv;
                acc[8]  += h2v.x * wv; acc[9]  += h2v.y * wv; acc[10] += h2v.z * wv; acc[11] += h2v.w * wv;
                acc[12] += h3v.x * wv; acc[13] += h3v.y * wv; acc[14] += h3v.z * wv; acc[15] += h3v.w * wv;
            }
#pragma unroll
            for (int r = 0; r < 16; r++) {
                size_t row = (size_t)row0 + r;
                float v = acc[r];
                if (c < DI) {
                    g_Z[row * DI + c] = siluf(v);
                } else if (c < 2 * DI) {
                    g_X[row * DI + (c - DI)] = siluf(v);
                } else if (c < 2 * DI + DS) {
                    g_Bm[row * DS + (c - 2 * DI)] = siluf(v);
                } else if (c < 2 * DI + 2 * DS) {
                    g_Cm[row * DS + (c - 2 * DI - DS)] = siluf(v);
                } else {
                    int hh = c - (2 * DI + 2 * DS);
                    g_dt[row * NH + hh] = softplusf(v + dt_bias[l * NH + hh]);
                }
            }
        }
    }
}

// ================= K3: per-chunk summary (Sdelta, aQ, la) =================
__global__ void k_chunk_summary(const float* __restrict__ A_log, int l) {
    const int bx = blockIdx.x;                 // = (b*NH + h)*NCH + ch
    const int ch = bx & (NCH - 1);
    const int h  = (bx >> 7) & 3;
    const int b  = bx >> 9;
    const size_t base = (size_t)b * L_ + (size_t)ch * Q;
    __shared__ float sX[Q][HD];
    __shared__ float sB[Q][DS];
    __shared__ float sla[Q], sw_[Q], sdt[Q];
    const int tid = threadIdx.x;               // 1024 threads

    for (int idx = tid; idx < Q * 32; idx += 1024) {
        int s = idx >> 5, j = idx & 31;
        sX[s][j] = g_X [(base + s) * DI + h * HD + j];
        sB[s][j] = g_Bm[(base + s) * DS + j];
    }
    if (tid < Q) sdt[tid] = g_dt[(base + tid) * NH + h];
    __syncthreads();

    const float A = -expf(A_log[l * NH + h]);
    if (tid < Q) {  // warp-parallel inclusive scan of dt*A (2 warps)
        float v = sdt[tid] * A;
#pragma unroll
        for (int o = 1; o < 32; o <<= 1) {
            float u = __shfl_up_sync(0xffffffffu, v, o);
            if ((tid & 31) >= o) v += u;
        }
        sla[tid] = v;
    }
    __syncthreads();
    if (tid >= 32 && tid < 64) sla[tid] += sla[31];
    __syncthreads();
    const float laQ = sla[Q - 1];
    if (tid < Q) {
        g_la[(base + tid) * NH + h] = sla[tid];
        sw_[tid] = sdt[tid] * __expf(laQ - sla[tid]);
    }
    __syncthreads();
    for (int idx = tid; idx < Q * HD; idx += 1024) {
        int s = idx >> 5;
        sX[s][idx & 31] *= sw_[s];
    }
    __syncthreads();

    const int p = tid >> 5, n = tid & 31;
    float acc = 0.f;
#pragma unroll
    for (int s = 0; s < Q; s++) acc += sX[s][p] * sB[s][n];
    g_Sd[(size_t)bx * 1024 + tid] = acc;
    if (tid == 0) g_aQ[bx] = __expf(laQ);
}

// ================= K4: sequential chunk-state recurrence =================
__global__ void k_chunk_scan() {
    const int bh = blockIdx.x;        // 64 blocks
    const int tid = threadIdx.x;      // 1024 threads, one state element each
    float hst = 0.f;
    const size_t base = (size_t)bh * NCH;
    for (int c = 0; c < NCH; c++) {
        size_t o = (base + c) * 1024 + tid;
        g_h0[o] = hst;
        hst = __ldg(&g_aQ[base + c]) * hst + g_Sd[o];
    }
}

// ================= K5: chunk output (G, Y, skip, gate) =================
__global__ void k_chunk_output(const float* __restrict__ Dp, int l) {
    const int bx = blockIdx.x;
    const int ch = bx & (NCH - 1);
    const int h  = (bx >> 7) & 3;
    const int b  = bx >> 9;
    const size_t base = (size_t)b * L_ + (size_t)ch * Q;
    __shared__ float sX[Q][33], sBm[Q][33], sCm[Q][33];
    __shared__ float sh0[HD][33];
    __shared__ float sla[Q], sdt[Q];
    __shared__ float sG[Q][Q + 1];
    const int tid = threadIdx.x;      // 256 threads

    for (int idx = tid; idx < Q * 32; idx += 256) {
        int s = idx >> 5, j = idx & 31;
        sX [s][j] = g_X [(base + s) * DI + h * HD + j];
        sBm[s][j] = g_Bm[(base + s) * DS + j];
        sCm[s][j] = g_Cm[(base + s) * DS + j];
    }
    for (int idx = tid; idx < HD * DS; idx += 256)
        sh0[idx >> 5][idx & 31] = g_h0[(size_t)bx * 1024 + idx];
    if (tid < Q) {
        sla[tid] = g_la[(base + tid) * NH + h];
        sdt[tid] = g_dt[(base + tid) * NH + h];
    }
    __syncthreads();

    // ---- G[t][s] = (C_t . B_s) * dt_s * exp(la_t - la_s), masked ----
    {
        const int tt = (tid >> 4) * 4;
        const int ss = (tid & 15) * 4;
        float a[4][4];
#pragma unroll
        for (int i = 0; i < 4; i++)
#pragma unroll
            for (int j = 0; j < 4; j++) a[i][j] = 0.f;
#pragma unroll
        for (int n = 0; n < 32; n++) {
            float cv0 = sCm[tt + 0][n], cv1 = sCm[tt + 1][n];
            float cv2 = sCm[tt + 2][n], cv3 = sCm[tt + 3][n];
            float bv0 = sBm[ss + 0][n], bv1 = sBm[ss + 1][n];
            float bv2 = sBm[ss + 2][n], bv3 = sBm[ss + 3][n];
            a[0][0] += cv0 * bv0; a[0][1] += cv0 * bv1; a[0][2] += cv0 * bv2; a[0][3] += cv0 * bv3;
            a[1][0] += cv1 * bv0; a[1][1] += cv1 * bv1; a[1][2] += cv1 * bv2; a[1][3] += cv1 * bv3;
            a[2][0] += cv2 * bv0; a[2][1] += cv2 * bv1; a[2][2] += cv2 * bv2; a[2][3] += cv2 * bv3;
            a[3][0] += cv3 * bv0; a[3][1] += cv3 * bv1; a[3][2] += cv3 * bv2; a[3][3] += cv3 * bv3;
        }
#pragma unroll
        for (int i = 0; i < 4; i++) {
            float lat = sla[tt + i];
#pragma unroll
            for (int j = 0; j < 4; j++) {
                int s = ss + j;
                float g = (s <= tt + i) ? a[i][j] * sdt[s] * __expf(lat - sla[s]) : 0.f;
                sG[tt + i][s] = g;
            }
        }
    }
    __syncthreads();

    // ---- Y[t][p] = exp(la_t)*(C_t . h0[p,:]) + sum_s G[t][s]*X[s][p] ----
    {
        const int p = tid & 31;
        const int tb = tid >> 5;              // 8 warps, 8 t-rows each
        float y[8];
#pragma unroll
        for (int i = 0; i < 8; i++) y[i] = 0.f;
#pragma unroll
        for (int n = 0; n < 32; n++) {
            float h0v = sh0[p][n];
#pragma unroll
            for (int i = 0; i < 8; i++) y[i] += sCm[tb * 8 + i][n] * h0v;
        }
#pragma unroll
        for (int i = 0; i < 8; i++) y[i] *= __expf(sla[tb * 8 + i]);
        for (int s = 0; s < Q; s++) {
            float xv = sX[s][p];
#pragma unroll
            for (int i = 0; i < 8; i++) y[i] += sG[tb * 8 + i][s] * xv;
        }
        const float Dh = Dp[l * NH + h];
#pragma unroll
        for (int i = 0; i < 8; i++) {
            int t = tb * 8 + i;
            size_t o = (base + t) * DI + h * HD + p;
            g_y[o] = (y[i] + Dh * sX[t][p]) * g_Z[o];
        }
    }
}

// ================= K6: out_proj + residual =================
__global__ void k_outproj(const float* __restrict__ Wo,  // [NL, DI, DM]
                          const float* __restrict__ bo,  // [NL, DM]
                          int l) {
    const int row0 = blockIdx.x * 16;
    __shared__ float sY[16][DI + 4];
    const int tid = threadIdx.x;
    for (int idx = tid; idx < 16 * DI; idx += 256) {
        int r = idx >> 7, k = idx & 127;
        sY[r][k] = g_y[(size_t)(row0 + r) * DI + k];
    }
    __syncthreads();
    const int c = tid & 63, q = tid >> 6;
    const float* Wl = Wo + (size_t)l * DI * DM;
    float acc[4] = {0.f, 0.f, 0.f, 0.f};
    for (int k = 0; k < DI; k++) {
        float wv = __ldg(&Wl[k * DM + c]);
#pragma unroll
        for (int j = 0; j < 4; j++) acc[j] += sY[q * 4 + j][k] * wv;
    }
    const float bc = bo[l * DM + c];
#pragma unroll
    for (int j = 0; j < 4; j++) {
        size_t o = (size_t)(row0 + q * 4 + j) * DM + c;
        g_h[o] = g_h[o] + acc[j] + bc;
    }
}

// ================= K7: mean-pool + classifier =================
__global__ void k_pool_cls(const float* __restrict__ cW,
                           const float* __restrict__ cb,
                           float* __restrict__ out) {
    const int b = blockIdx.x;
    const int tid = threadIdx.x;   // 256
    const int d = tid & 63, part = tid >> 6;
    double s = 0.0;
    for (int ll = part; ll < L_; ll += 4)
        s += (double)g_h[((size_t)b * L_ + ll) * DM + d];
    __shared__ double red[4][64];
    __shared__ double pooled[64];
    red[part][d] = s;
    __syncthreads();
    if (tid < 64)
        pooled[tid] = (red[0][tid] + red[1][tid] + red[2][tid] + red[3][tid]) / (double)L_;
    __syncthreads();
    if (tid < OUT_) {
        double acc = (double)cb[tid];
        for (int dd = 0; dd < DM; dd++)
            acc += pooled[dd] * (double)cW[dd * OUT_ + tid];
        out[b * OUT_ + tid] = (float)acc;
    }
}

// ================= launch =================
extern "C" void kernel_launch(void* const* d_in, const int* in_sizes, int n_in,
                              void* d_out, int out_size) {
    const float* x        = (const float*)d_in[0];
    const float* W_in     = (const float*)d_in[1];
    const float* b_in     = (const float*)d_in[2];
    const float* in_proj_W= (const float*)d_in[3];
    const float* in_proj_b= (const float*)d_in[4];
    const float* A_log    = (const float*)d_in[5];
    const float* Dp       = (const float*)d_in[6];
    const float* dt_bias  = (const float*)d_in[7];
    const float* out_proj_W = (const float*)d_in[8];
    const float* out_proj_b = (const float*)d_in[9];
    const float* cls_W    = (const float*)d_in[10];
    const float* cls_b    = (const float*)d_in[11];
    float* out = (float*)d_out;

    k_linear_in<<<BL / 16, 256>>>(x, W_in, b_in);
    for (int l = 0; l < NL; l++) {
        k_inproj<<<BL / 16, 256>>>(in_proj_W, in_proj_b, dt_bias, l);
        k_chunk_summary<<<B_ * NH * NCH, 1024>>>(A_log, l);
        k_chunk_scan<<<B_ * NH, 1024>>>();
        k_chunk_output<<<B_ * NH * NCH, 256>>>(Dp, l);
        k_outproj<<<BL / 16, 256>>>(out_proj_W, out_proj_b, l);
    }
    k_pool_cls<<<B_, 256>>>(cls_W, cls_b, out);
}